// round 9
// baseline (speedup 1.0000x reference)
#include <cuda_runtime.h>

// OpticalFlowLK 2048x2048 fp32. Register-rolling vertical scan, float2 per
// lane, TWO output rows per iteration (shared products qb,qc between rows)
// for ILP. Warp shuffles for horizontal exchange. No shared memory.

#define IMH 2048
#define IMW 2048
#define ROW2 (IMW / 2)          // row stride in float2
#define STRIP 16
#define WPB 4
#define WOUT 60                 // output columns per warp
#define NGROUPS 35              // ceil(2048 / 60)
#define FULL 0xffffffffu

struct P5 { float2 xx, yy, xy, xt, yt; };

__device__ __forceinline__ int rowclamp(int r) {
    if (r < 0) return 0;
    if (r == IMH) return IMH - 2;   // reflect-after
    if (r > IMH) return 0;
    return r;
}

// Gradients scaled 2x vs reference (0.5 dropped): all tensor sums scale 4x
// uniformly, so u, v and the det==0 set are unchanged.
__device__ __forceinline__ P5 prodrow_i(float2 tP, float2 bP, float2 tN, float2 bN) {
    float sP0 = tP.x + bP.x, sP1 = tP.y + bP.y;
    float dP0 = bP.x - tP.x, dP1 = bP.y - tP.y;
    float sN0 = tN.x + bN.x, sN1 = tN.y + bN.y;
    float dN0 = bN.x - tN.x, dN1 = bN.y - tN.y;
    float S0 = sP0 + sN0, S1 = sP1 + sN1;
    float D0 = dP0 + dN0, D1 = dP1 + dN1;
    float T0 = sN0 - sP0, T1 = sN1 - sP1;
    float Sn = __shfl_down_sync(FULL, S0, 1);
    float Dn = __shfl_down_sync(FULL, D0, 1);
    float Tn = __shfl_down_sync(FULL, T0, 1);
    float rx0 = S1 - S0, rx1 = Sn - S1;
    float ry0 = D0 + D1, ry1 = D1 + Dn;
    float rt0 = T0 + T1, rt1 = T1 + Tn;
    P5 q;
    q.xx = make_float2(rx0 * rx0, rx1 * rx1);
    q.yy = make_float2(ry0 * ry0, ry1 * ry1);
    q.xy = make_float2(rx0 * ry0, rx1 * ry1);
    q.xt = make_float2(rt0 * rx0, rt1 * rx1);
    q.yt = make_float2(rt0 * ry0, rt1 * ry1);
    return q;
}

__device__ __forceinline__ P5 p5add(const P5& a, const P5& b) {
    P5 r;
    r.xx = make_float2(a.xx.x + b.xx.x, a.xx.y + b.xx.y);
    r.yy = make_float2(a.yy.x + b.yy.x, a.yy.y + b.yy.y);
    r.xy = make_float2(a.xy.x + b.xy.x, a.xy.y + b.xy.y);
    r.xt = make_float2(a.xt.x + b.xt.x, a.xt.y + b.xt.y);
    r.yt = make_float2(a.yt.x + b.yt.x, a.yt.y + b.yt.y);
    return r;
}

__device__ __forceinline__ float2 hbox(float2 V) {
    float pv = __shfl_up_sync(FULL, V.y, 1);
    float nv = __shfl_down_sync(FULL, V.x, 1);
    float m = V.x + V.y;
    return make_float2(pv + m, m + nv);
}

__device__ __forceinline__ void solve1(float Sxx, float Syy, float Sxy,
                                       float Sxt, float Syt,
                                       float& u, float& v) {
    float det = Sxx * Syy - Sxy * Sxy;
    u = 0.f; v = 0.f;
    if (det != 0.f) {
        float inv = __fdividef(1.0f, det);
        u = (Syy * Sxt - Sxy * Syt) * inv;
        v = (Sxx * Syt - Sxy * Sxt) * inv;
    }
}

// Row r's box sums + solve + store from V channels.
__device__ __forceinline__ void row_finish(const P5& V, bool storelane,
                                           float2* outU, float2* outV, size_t o) {
    float2 Sxx = hbox(V.xx);
    float2 Syy = hbox(V.yy);
    float2 Sxy = hbox(V.xy);
    float2 Sxt = hbox(V.xt);
    float2 Syt = hbox(V.yt);
    float2 u2, v2;
    solve1(Sxx.x, Syy.x, Sxy.x, Sxt.x, Syt.x, u2.x, v2.x);
    solve1(Sxx.y, Syy.y, Sxy.y, Sxt.y, Syt.y, u2.y, v2.y);
    if (storelane) {
        outU[o] = u2;
        outV[o] = v2;
    }
}

// ---------------- edge helpers (general path, validated) ----------------

__device__ __forceinline__ void loadrow(const float* __restrict__ P,
                                        const float* __restrict__ N,
                                        size_t rb, int c0, int cc0, int cc1,
                                        bool vec, float2& p, float2& n) {
    if (vec) {
        p = *reinterpret_cast<const float2*>(P + rb + c0);
        n = *reinterpret_cast<const float2*>(N + rb + c0);
    } else {
        p.x = P[rb + cc0]; p.y = P[rb + cc1];
        n.x = N[rb + cc0]; n.y = N[rb + cc1];
    }
}

__device__ __forceinline__ P5 prodrow_e(float2 tP, float2 bP, float2 tN, float2 bN,
                                        bool v0, bool v1) {
    float sP0 = tP.x + bP.x, sP1 = tP.y + bP.y;
    float dP0 = bP.x - tP.x, dP1 = bP.y - tP.y;
    float sN0 = tN.x + bN.x, sN1 = tN.y + bN.y;
    float dN0 = bN.x - tN.x, dN1 = bN.y - tN.y;
    float S0 = sP0 + sN0, S1 = sP1 + sN1;
    float D0 = dP0 + dN0, D1 = dP1 + dN1;
    float T0 = sN0 - sP0, T1 = sN1 - sP1;
    float Sn = __shfl_down_sync(FULL, S0, 1);
    float Dn = __shfl_down_sync(FULL, D0, 1);
    float Tn = __shfl_down_sync(FULL, T0, 1);
    float rx0 = S1 - S0, rx1 = Sn - S1;
    float ry0 = D0 + D1, ry1 = D1 + Dn;
    float rt0 = T0 + T1, rt1 = T1 + Tn;
    P5 q;
    q.xx.x = v0 ? rx0 * rx0 : 0.f;  q.xx.y = v1 ? rx1 * rx1 : 0.f;
    q.yy.x = v0 ? ry0 * ry0 : 0.f;  q.yy.y = v1 ? ry1 * ry1 : 0.f;
    q.xy.x = v0 ? rx0 * ry0 : 0.f;  q.xy.y = v1 ? rx1 * ry1 : 0.f;
    q.xt.x = v0 ? rt0 * rx0 : 0.f;  q.xt.y = v1 ? rt1 * rx1 : 0.f;
    q.yt.x = v0 ? rt0 * ry0 : 0.f;  q.yt.y = v1 ? rt1 * ry1 : 0.f;
    return q;
}

__global__ __launch_bounds__(32 * WPB)
void lk_flow_kernel(const float* __restrict__ prev,
                    const float* __restrict__ next,
                    float* __restrict__ out) {
    const int lane = threadIdx.x;
    const int g = blockIdx.x * WPB + threadIdx.y;
    if (g >= NGROUPS) return;

    const int ob = g * WOUT;
    const int r0 = blockIdx.y * STRIP;
    const bool storelane = (lane >= 1) && (lane <= 30);

    const bool interior = (g >= 1) && (g <= 33) &&
                          (blockIdx.y >= 1) && (blockIdx.y <= 126);

    float2* outU = reinterpret_cast<float2*>(out);
    float2* outV = reinterpret_cast<float2*>(out + (size_t)IMH * IMW);

    if (interior) {
        // ---------------- FAST PATH: 2 rows per iteration ----------------
        const int cidx = ((ob - 2) >> 1) + lane;
        const float2* P2 = reinterpret_cast<const float2*>(prev)
                           + (size_t)(r0 - 1) * ROW2 + cidx;
        const float2* N2 = reinterpret_cast<const float2*>(next)
                           + (size_t)(r0 - 1) * ROW2 + cidx;

        float2 i0p = P2[0];        float2 i0n = N2[0];        // row r0-1
        float2 i1p = P2[ROW2];     float2 i1n = N2[ROW2];     // row r0
        float2 i2p = P2[2 * ROW2]; float2 i2n = N2[2 * ROW2]; // row r0+1

        P5 qa = prodrow_i(i0p, i1p, i0n, i1n);   // q(r0-1)
        P5 qb = prodrow_i(i1p, i2p, i1n, i2n);   // q(r0)

        float2 Ap = i2p, An = i2n;               // image row r+1 (r = r0)
        const float2* Pf = P2 + 3 * ROW2;        // row r0+2
        const float2* Nf = N2 + 3 * ROW2;

        size_t o = (size_t)r0 * ROW2 + cidx;

        #pragma unroll 2
        for (int it = 0; it < STRIP / 2; ++it) {
            float2 Bp = Pf[0],    Bn = Nf[0];      // row r+2
            float2 Cp = Pf[ROW2], Cn = Nf[ROW2];   // row r+3
            Pf += 2 * ROW2; Nf += 2 * ROW2;

            P5 qc = prodrow_i(Ap, Bp, An, Bn);     // q(r+1)
            P5 qd = prodrow_i(Bp, Cp, Bn, Cn);     // q(r+2)

            P5 t  = p5add(qb, qc);                 // shared middle pair
            P5 V0 = p5add(qa, t);                  // row r
            P5 V1 = p5add(t, qd);                  // row r+1

            row_finish(V0, storelane, outU, outV, o);
            row_finish(V1, storelane, outU, outV, o + ROW2);
            o += 2 * ROW2;

            qa = qc; qb = qd;
            Ap = Cp; An = Cn;
        }
        return;
    }

    // ---------------- EDGE PATH (general, validated) ----------------
    const int c0 = ob - 2 + 2 * lane;
    const int c1 = c0 + 1;
    int cc0 = c0;
    if (cc0 < 0) cc0 = 0; else if (cc0 >= IMW) cc0 = (cc0 == IMW) ? IMW - 2 : 0;
    int cc1 = c1;
    if (cc1 < 0) cc1 = 0; else if (cc1 >= IMW) cc1 = (cc1 == IMW) ? IMW - 2 : 0;
    const bool vec = (c0 >= 0) && (c1 < IMW);
    const bool cv0 = (c0 >= 0) && (c0 < IMW);
    const bool cv1 = (c1 >= 0) && (c1 < IMW);

    float2 i0p, i0n, i1p, i1n, i2p, i2n;
    loadrow(prev, next, (size_t)rowclamp(r0 - 1) * IMW, c0, cc0, cc1, vec, i0p, i0n);
    loadrow(prev, next, (size_t)r0 * IMW,               c0, cc0, cc1, vec, i1p, i1n);
    P5 qa = prodrow_e(i0p, i1p, i0n, i1n, cv0 && (r0 > 0), cv1 && (r0 > 0));

    loadrow(prev, next, (size_t)(r0 + 1) * IMW,         c0, cc0, cc1, vec, i2p, i2n);
    P5 qb = prodrow_e(i1p, i2p, i1n, i2n, cv0, cv1);

    float2 Ap = i2p, An = i2n, Bp, Bn;
    loadrow(prev, next, (size_t)(r0 + 2) * IMW,         c0, cc0, cc1, vec, Bp, Bn);

    const bool st = storelane && (c0 < IMW);

    for (int r = r0; r < r0 + STRIP; ++r) {
        float2 Cp, Cn;
        loadrow(prev, next, (size_t)rowclamp(r + 3) * IMW, c0, cc0, cc1, vec, Cp, Cn);

        const bool rv = (r + 1 < IMH);
        P5 qc = prodrow_e(Ap, Bp, An, Bn, cv0 && rv, cv1 && rv);

        P5 V = p5add(p5add(qa, qb), qc);

        float2 Sxx = hbox(V.xx);
        float2 Syy = hbox(V.yy);
        float2 Sxy = hbox(V.xy);
        float2 Sxt = hbox(V.xt);
        float2 Syt = hbox(V.yt);

        float u0, v0, u1, v1;
        solve1(Sxx.x, Syy.x, Sxy.x, Sxt.x, Syt.x, u0, v0);
        solve1(Sxx.y, Syy.y, Sxy.y, Sxt.y, Syt.y, u1, v1);
        if (r == 0) { u0 = u1 = v0 = v1 = 0.f; }
        if (c0 == 0) { u0 = 0.f; v0 = 0.f; }

        if (st) {
            const size_t o = ((size_t)r * IMW + c0) >> 1;
            outU[o] = make_float2(u0, u1);
            outV[o] = make_float2(v0, v1);
        }

        qa = qb; qb = qc;
        Ap = Bp; An = Bn;
        Bp = Cp; Bn = Cn;
    }
}

extern "C" void kernel_launch(void* const* d_in, const int* in_sizes, int n_in,
                              void* d_out, int out_size) {
    const float* prev = (const float*)d_in[0];
    const float* next = (const float*)d_in[1];
    float* out = (float*)d_out;
    dim3 block(32, WPB, 1);
    dim3 grid((NGROUPS + WPB - 1) / WPB, IMH / STRIP, 1);
    lk_flow_kernel<<<grid, block>>>(prev, next, out);
}

// round 10
// speedup vs baseline: 1.0340x; 1.0340x over previous
#include <cuda_runtime.h>

// OpticalFlowLK 2048x2048 fp32 — shuffle-free formulation.
// Each lane owns 2 output columns and loads its own 5-pixel window (3 aligned
// float2 cells) per image row. Horizontal-first box sums -> only 10 rolling
// registers of H state; vertical 3-sum via register rolling. No smem, no SHFL.

#define IMH 2048
#define IMW 2048
#define CELLS 1024            // float2 cells per image row
#define STRIP 16
#define WPB 4

struct Row5 { float e[5]; float f[5]; };   // E=P+N, F=N-P at 5 pixel cols
struct H10 { float v[10]; };               // xx0,xx1,yy0,yy1,xy0,xy1,xt0,xt1,yt0,yt1

// Gradients scaled 2x vs reference (0.5 dropped): all tensor sums scale 4x
// uniformly, so u, v and the det==0 set are unchanged.

__device__ __forceinline__ int rowclamp(int r) {
    if (r < 0) return 0;
    if (r == IMH) return IMH - 2;   // reflect-after
    if (r > IMH) return 0;
    return r;
}
__device__ __forceinline__ int clampcol(int c) {
    if (c < 0) return 0;
    if (c == IMW) return IMW - 2;   // reflect-after
    if (c > IMW) return 0;
    return c;
}

__device__ __forceinline__ Row5 makeRow(float2 Lp, float2 Mp, float2 Rp,
                                        float2 Ln, float2 Mn, float2 Rn) {
    float p[5] = {Lp.y, Mp.x, Mp.y, Rp.x, Rp.y};
    float n[5] = {Ln.y, Mn.x, Mn.y, Rn.x, Rn.y};
    Row5 r;
#pragma unroll
    for (int k = 0; k < 5; k++) { r.e[k] = p[k] + n[k]; r.f[k] = n[k] - p[k]; }
    return r;
}

// Products for one product row at 4 cols + immediate horizontal 3-sums.
__device__ __forceinline__ H10 prodH(const Row5& a, const Row5& b) {
    float S[5], D[5], T[5];
#pragma unroll
    for (int k = 0; k < 5; k++) {
        S[k] = a.e[k] + b.e[k];
        D[k] = b.e[k] - a.e[k];
        T[k] = a.f[k] + b.f[k];
    }
    float xx[4], yy[4], xy[4], xt[4], yt[4];
#pragma unroll
    for (int k = 0; k < 4; k++) {
        float rx = S[k + 1] - S[k];
        float ry = D[k] + D[k + 1];
        float rt = T[k] + T[k + 1];
        xx[k] = rx * rx; yy[k] = ry * ry; xy[k] = rx * ry;
        xt[k] = rt * rx; yt[k] = rt * ry;
    }
    H10 h;
    float m;
    m = xx[1] + xx[2]; h.v[0] = xx[0] + m; h.v[1] = m + xx[3];
    m = yy[1] + yy[2]; h.v[2] = yy[0] + m; h.v[3] = m + yy[3];
    m = xy[1] + xy[2]; h.v[4] = xy[0] + m; h.v[5] = m + xy[3];
    m = xt[1] + xt[2]; h.v[6] = xt[0] + m; h.v[7] = m + xt[3];
    m = yt[1] + yt[2]; h.v[8] = yt[0] + m; h.v[9] = m + yt[3];
    return h;
}

// Masked variant (per-product-col validity, incl. row validity).
__device__ __forceinline__ H10 prodHm(const Row5& a, const Row5& b,
                                      const bool* valid) {
    float S[5], D[5], T[5];
#pragma unroll
    for (int k = 0; k < 5; k++) {
        S[k] = a.e[k] + b.e[k];
        D[k] = b.e[k] - a.e[k];
        T[k] = a.f[k] + b.f[k];
    }
    float xx[4], yy[4], xy[4], xt[4], yt[4];
#pragma unroll
    for (int k = 0; k < 4; k++) {
        float rx = S[k + 1] - S[k];
        float ry = D[k] + D[k + 1];
        float rt = T[k] + T[k + 1];
        xx[k] = valid[k] ? rx * rx : 0.f;
        yy[k] = valid[k] ? ry * ry : 0.f;
        xy[k] = valid[k] ? rx * ry : 0.f;
        xt[k] = valid[k] ? rt * rx : 0.f;
        yt[k] = valid[k] ? rt * ry : 0.f;
    }
    H10 h;
    float m;
    m = xx[1] + xx[2]; h.v[0] = xx[0] + m; h.v[1] = m + xx[3];
    m = yy[1] + yy[2]; h.v[2] = yy[0] + m; h.v[3] = m + yy[3];
    m = xy[1] + xy[2]; h.v[4] = xy[0] + m; h.v[5] = m + xy[3];
    m = xt[1] + xt[2]; h.v[6] = xt[0] + m; h.v[7] = m + xt[3];
    m = yt[1] + yt[2]; h.v[8] = yt[0] + m; h.v[9] = m + yt[3];
    return h;
}

__device__ __forceinline__ void solve1(float Sxx, float Syy, float Sxy,
                                       float Sxt, float Syt,
                                       float& u, float& v) {
    float det = Sxx * Syy - Sxy * Sxy;
    u = 0.f; v = 0.f;
    if (det != 0.f) {
        float inv = __fdividef(1.0f, det);
        u = (Syy * Sxt - Sxy * Syt) * inv;
        v = (Sxx * Syt - Sxy * Sxt) * inv;
    }
}

__device__ __forceinline__ void finish(const H10& a, const H10& b, const H10& c,
                                       float2& u2, float2& v2) {
    float s[10];
#pragma unroll
    for (int k = 0; k < 10; k++) s[k] = a.v[k] + b.v[k] + c.v[k];
    solve1(s[0], s[2], s[4], s[6], s[8], u2.x, v2.x);
    solve1(s[1], s[3], s[5], s[7], s[9], u2.y, v2.y);
}

__device__ __forceinline__ Row5 loadRowE(const float* __restrict__ prev,
                                         const float* __restrict__ next,
                                         int rr, const int* pc) {
    float p[5], n[5];
    size_t rb = (size_t)rr * IMW;
#pragma unroll
    for (int k = 0; k < 5; k++) { p[k] = prev[rb + pc[k]]; n[k] = next[rb + pc[k]]; }
    Row5 r;
#pragma unroll
    for (int k = 0; k < 5; k++) { r.e[k] = p[k] + n[k]; r.f[k] = n[k] - p[k]; }
    return r;
}

__global__ __launch_bounds__(32 * WPB)
void lk_flow_kernel(const float* __restrict__ prev,
                    const float* __restrict__ next,
                    float* __restrict__ out) {
    const int lane = threadIdx.x;
    const int g = blockIdx.x * WPB + threadIdx.y;   // column group 0..31
    const int j = g * 32 + lane;                    // float2 cell index 0..1023
    const int c0 = 2 * j;                           // output columns c0, c0+1
    const int r0 = blockIdx.y * STRIP;

    float2* outU = reinterpret_cast<float2*>(out);
    float2* outV = reinterpret_cast<float2*>(out + (size_t)IMH * IMW);

    const bool interior = (g >= 1) && (g <= 30) &&
                          (blockIdx.y >= 1) && (blockIdx.y <= (IMH / STRIP) - 2);

    if (interior) {
        // ---------------- FAST PATH: branchless, shuffle-free ----------------
        const float2* P2 = reinterpret_cast<const float2*>(prev)
                           + (size_t)(r0 - 1) * CELLS + (j - 1);
        const float2* N2 = reinterpret_cast<const float2*>(next)
                           + (size_t)(r0 - 1) * CELLS + (j - 1);

        Row5 rm = makeRow(P2[0], P2[1], P2[2], N2[0], N2[1], N2[2]);  // row r0-1
        P2 += CELLS; N2 += CELLS;
        Row5 rc = makeRow(P2[0], P2[1], P2[2], N2[0], N2[1], N2[2]);  // row r0
        P2 += CELLS; N2 += CELLS;
        Row5 ra = makeRow(P2[0], P2[1], P2[2], N2[0], N2[1], N2[2]);  // row r0+1
        P2 += CELLS; N2 += CELLS;                                     // -> row r0+2

        H10 h0 = prodH(rm, rc);   // product row r0-1
        H10 h1 = prodH(rc, ra);   // product row r0

        size_t o = (size_t)r0 * CELLS + j;

        #pragma unroll 4
        for (int it = 0; it < STRIP; ++it) {
            float2 Lp = P2[0], Mp = P2[1], Rp = P2[2];
            float2 Ln = N2[0], Mn = N2[1], Rn = N2[2];
            P2 += CELLS; N2 += CELLS;

            Row5 rb = makeRow(Lp, Mp, Rp, Ln, Mn, Rn);
            H10 h2 = prodH(ra, rb);              // product row r+1

            float2 u2, v2;
            finish(h0, h1, h2, u2, v2);
            outU[o] = u2;
            outV[o] = v2;
            o += CELLS;

            h0 = h1; h1 = h2; ra = rb;
        }
        return;
    }

    // ---------------- EDGE PATH: clamped scalar loads + validity ----------------
    int pc[5];
    bool cvp[4];
#pragma unroll
    for (int k = 0; k < 5; k++) pc[k] = clampcol(c0 - 1 + k);
#pragma unroll
    for (int k = 0; k < 4; k++) {
        int c = c0 - 1 + k;
        cvp[k] = (c >= 0) && (c < IMW);
    }

    Row5 rm = loadRowE(prev, next, rowclamp(r0 - 1), pc);
    Row5 rc = loadRowE(prev, next, r0, pc);
    Row5 ra = loadRowE(prev, next, r0 + 1, pc);

    bool vm[4];
#pragma unroll
    for (int k = 0; k < 4; k++) vm[k] = cvp[k] && (r0 > 0);
    H10 h0 = prodHm(rm, rc, vm);    // product row r0-1
    H10 h1 = prodHm(rc, ra, cvp);   // product row r0 (always in range)

    size_t o = (size_t)r0 * CELLS + j;

    for (int r = r0; r < r0 + STRIP; ++r) {
        Row5 rb = loadRowE(prev, next, rowclamp(r + 2), pc);

        bool vb[4];
        const bool rv = (r + 1 < IMH);
#pragma unroll
        for (int k = 0; k < 4; k++) vb[k] = cvp[k] && rv;
        H10 h2 = prodHm(ra, rb, vb);            // product row r+1

        float2 u2, v2;
        finish(h0, h1, h2, u2, v2);
        if (r == 0) { u2 = make_float2(0.f, 0.f); v2 = make_float2(0.f, 0.f); }
        if (c0 == 0) { u2.x = 0.f; v2.x = 0.f; }

        outU[o] = u2;
        outV[o] = v2;
        o += CELLS;

        h0 = h1; h1 = h2; ra = rb;
    }
}

extern "C" void kernel_launch(void* const* d_in, const int* in_sizes, int n_in,
                              void* d_out, int out_size) {
    const float* prev = (const float*)d_in[0];
    const float* next = (const float*)d_in[1];
    float* out = (float*)d_out;
    dim3 block(32, WPB, 1);
    dim3 grid(32 / WPB, IMH / STRIP, 1);
    lk_flow_kernel<<<grid, block>>>(prev, next, out);
}